// round 1
// baseline (speedup 1.0000x reference)
#include <cuda_runtime.h>

#define NTHR   256
#define KKB    288
#define NC     32
#define EPS    1e-6f
#define LAM    1e-3f
#define LN2PI  1.8378770664093453f

// shared-memory float offsets
#define SM_POSE 0                    // 288*20
#define SM_ACT  (KKB*20)             // 5760, size 288
#define SM_R    (SM_ACT + KKB)       // 6048, size 288*33
#define SM_MU   (SM_R + KKB*33)      // 15552, size 512
#define SM_ISIG (SM_MU + 512)        // 16064, size 512
#define SM_AOUT (SM_ISIG + 512)      // 16576
#define SM_CC   (SM_AOUT + 32)       // 16608
#define SM_RSUM (SM_CC + 32)         // 16640
#define SM_INVR (SM_RSUM + 32)       // 16672
#define SM_RED  (SM_INVR + 32)       // 16704
#define SM_TOTAL (SM_RED + 32)       // 16736 floats = 66944 bytes

__device__ __forceinline__ float4 vrow(const float4 p, const float4 w0,
                                       const float4 w1, const float4 w2,
                                       const float4 w3) {
    float4 v;
    v.x = fmaf(p.x, w0.x, fmaf(p.y, w1.x, fmaf(p.z, w2.x, p.w * w3.x)));
    v.y = fmaf(p.x, w0.y, fmaf(p.y, w1.y, fmaf(p.z, w2.y, p.w * w3.y)));
    v.z = fmaf(p.x, w0.z, fmaf(p.y, w1.z, fmaf(p.z, w2.z, p.w * w3.z)));
    v.w = fmaf(p.x, w0.w, fmaf(p.y, w1.w, fmaf(p.z, w2.w, p.w * w3.w)));
    return v;
}

__device__ __forceinline__ void macc(float coeff, const float4 v, float4& mu, float4& s2) {
    float cx = coeff * v.x, cy = coeff * v.y, cz = coeff * v.z, cw = coeff * v.w;
    mu.x += cx; mu.y += cy; mu.z += cz; mu.w += cw;
    s2.x = fmaf(cx, v.x, s2.x); s2.y = fmaf(cy, v.y, s2.y);
    s2.z = fmaf(cz, v.z, s2.z); s2.w = fmaf(cw, v.w, s2.w);
}

__device__ __forceinline__ void red8(float4& v) {
    #pragma unroll
    for (int d = 4; d; d >>= 1) {
        v.x += __shfl_down_sync(0xffffffffu, v.x, d, 8);
        v.y += __shfl_down_sync(0xffffffffu, v.y, d, 8);
        v.z += __shfl_down_sync(0xffffffffu, v.z, d, 8);
        v.w += __shfl_down_sync(0xffffffffu, v.w, d, 8);
    }
}

__global__ void __launch_bounds__(NTHR, 2)
convcaps_kernel(const float* __restrict__ gx, const float* __restrict__ ga,
                const float* __restrict__ gw, const float* __restrict__ gbu,
                const float* __restrict__ gba, float* __restrict__ gout)
{
    extern __shared__ float sm[];
    const int tid = threadIdx.x;
    const int blk = blockIdx.x;            // 288 positions: b*36 + h*6 + w
    const int b   = blk / 36;
    const int hw  = blk - b * 36;
    const int h2  = (hw / 6) * 2;
    const int w2  = (hw % 6) * 2;

    // ---- load pose patch (288 rows x 16 floats, padded to 20) ----
    for (int idx = tid; idx < KKB * 4; idx += NTHR) {
        int n = idx >> 2, q = idx & 3;
        int ki = n / 96; int rem = n - ki * 96;
        int kj = rem >> 5; int bi = rem & 31;
        const float4* src = (const float4*)(gx +
            (size_t)((b * 14 + h2 + ki) * 14 + (w2 + kj)) * 512 + bi * 16);
        *(float4*)(sm + SM_POSE + n * 20 + q * 4) = src[q];
    }
    for (int n = tid; n < KKB; n += NTHR) {
        int ki = n / 96; int rem = n - ki * 96;
        int kj = rem >> 5; int bi = rem & 31;
        sm[SM_ACT + n] = ga[((b * 14 + h2 + ki) * 14 + (w2 + kj)) * 32 + bi];
    }
    __syncthreads();

    // ---- iter0 init: r[n][c] = act[n]/C ; rsum (same for all c) ----
    for (int idx = tid; idx < KKB * NC; idx += NTHR) {
        int n = idx >> 5, cc = idx & 31;
        sm[SM_R + n * 33 + cc] = sm[SM_ACT + n] * (1.0f / 32.0f);
    }
    if (tid < 32) {
        float s = 0.f;
        for (int n = tid; n < KKB; n += 32) s += sm[SM_ACT + n];
        #pragma unroll
        for (int d = 16; d; d >>= 1) s += __shfl_down_sync(0xffffffffu, s, d);
        if (tid == 0) sm[SM_RED] = s * (1.0f / 32.0f);
    }
    __syncthreads();
    if (tid < 32) {
        float r0 = sm[SM_RED];
        sm[SM_RSUM + tid] = r0;
        sm[SM_INVR + tid] = 1.f / (r0 + EPS);
    }
    __syncthreads();

    const int c = tid >> 3;     // output capsule handled by this 8-lane group
    const int k = tid & 7;      // lane within group

    for (int it = 0; it < 3; ++it) {
        // ================= M step =================
        {
            const float invr = sm[SM_INVR + c];
            const float rsum = sm[SM_RSUM + c];
            const float sfac = rsum * invr;            // sum of coeff over n
            float4 mu0 = make_float4(0,0,0,0), mu1 = mu0, mu2 = mu0, mu3 = mu0;
            float4 s20 = mu0, s21 = mu0, s22 = mu0, s23 = mu0;
            #pragma unroll 2
            for (int n = k; n < KKB; n += 8) {
                float coeff = sm[SM_R + n * 33 + c] * invr;
                const float4* pr = (const float4*)(sm + SM_POSE + n * 20);
                float4 p0 = pr[0], p1 = pr[1], p2 = pr[2], p3 = pr[3];
                const float4* wr = (const float4*)(gw + ((size_t)n * 32 + c) * 16);
                float4 w0 = wr[0], w1 = wr[1], w2 = wr[2], w3 = wr[3];
                macc(coeff, vrow(p0, w0, w1, w2, w3), mu0, s20);
                macc(coeff, vrow(p1, w0, w1, w2, w3), mu1, s21);
                macc(coeff, vrow(p2, w0, w1, w2, w3), mu2, s22);
                macc(coeff, vrow(p3, w0, w1, w2, w3), mu3, s23);
            }
            red8(mu0); red8(mu1); red8(mu2); red8(mu3);
            red8(s20); red8(s21); red8(s22); red8(s23);
            if (k == 0) {
                float* smu = sm + SM_MU + c * 16;
                float* sis = sm + SM_ISIG + c * 16;
                const float t2s = 2.0f - sfac;
                float sumlog = 0.f;
                #define FIN(P, MUV, S2V) { float m_ = (MUV); \
                    float sg = (S2V) - m_ * m_ * t2s + EPS;  \
                    smu[P] = m_; sis[P] = 0.5f / sg; sumlog += __logf(sg); }
                FIN(0,  mu0.x, s20.x) FIN(1,  mu0.y, s20.y)
                FIN(2,  mu0.z, s20.z) FIN(3,  mu0.w, s20.w)
                FIN(4,  mu1.x, s21.x) FIN(5,  mu1.y, s21.y)
                FIN(6,  mu1.z, s21.z) FIN(7,  mu1.w, s21.w)
                FIN(8,  mu2.x, s22.x) FIN(9,  mu2.y, s22.y)
                FIN(10, mu2.z, s22.z) FIN(11, mu2.w, s22.w)
                FIN(12, mu3.x, s23.x) FIN(13, mu3.y, s23.y)
                FIN(14, mu3.z, s23.z) FIN(15, mu3.w, s23.w)
                #undef FIN
                float cost = rsum * (16.0f * gbu[c] + 0.5f * sumlog);
                float ao = 1.0f / (1.0f + __expf(LAM * (cost - gba[c])));
                sm[SM_AOUT + c] = ao;
                sm[SM_CC + c] = __logf(ao) - 0.5f * sumlog - 8.0f * LN2PI;
            }
        }
        __syncthreads();
        if (it == 2) break;

        // ================= E step =================
        {
            float mur[16], isr[16];
            #pragma unroll
            for (int p = 0; p < 16; ++p) {
                mur[p] = sm[SM_MU + c * 16 + p];
                isr[p] = sm[SM_ISIG + c * 16 + p];
            }
            const float ccst = sm[SM_CC + c];
            #pragma unroll 2
            for (int n = k; n < KKB; n += 8) {
                const float4* pr = (const float4*)(sm + SM_POSE + n * 20);
                float4 p0 = pr[0], p1 = pr[1], p2 = pr[2], p3 = pr[3];
                const float4* wr = (const float4*)(gw + ((size_t)n * 32 + c) * 16);
                float4 w0 = wr[0], w1 = wr[1], w2 = wr[2], w3 = wr[3];
                float4 acc = make_float4(0,0,0,0);
                #define EACC(VI, OFF) { float4 v_ = (VI); \
                    float dx = v_.x - mur[(OFF)+0], dy = v_.y - mur[(OFF)+1]; \
                    float dz = v_.z - mur[(OFF)+2], dw = v_.w - mur[(OFF)+3]; \
                    acc.x = fmaf(dx, dx * isr[(OFF)+0], acc.x); \
                    acc.y = fmaf(dy, dy * isr[(OFF)+1], acc.y); \
                    acc.z = fmaf(dz, dz * isr[(OFF)+2], acc.z); \
                    acc.w = fmaf(dw, dw * isr[(OFF)+3], acc.w); }
                EACC(vrow(p0, w0, w1, w2, w3), 0)
                EACC(vrow(p1, w0, w1, w2, w3), 4)
                EACC(vrow(p2, w0, w1, w2, w3), 8)
                EACC(vrow(p3, w0, w1, w2, w3), 12)
                #undef EACC
                sm[SM_R + n * 33 + c] = ccst - (acc.x + acc.y + acc.z + acc.w);
            }
        }
        __syncthreads();

        // softmax over c (axis 4) per n
        for (int n = tid; n < KKB; n += NTHR) {
            float* row = sm + SM_R + n * 33;
            float e[32];
            float m = row[0];
            #pragma unroll
            for (int j = 1; j < 32; ++j) m = fmaxf(m, row[j]);
            float s = 0.f;
            #pragma unroll
            for (int j = 0; j < 32; ++j) { e[j] = __expf(row[j] - m); s += e[j]; }
            float inv = 1.0f / s;
            #pragma unroll
            for (int j = 0; j < 32; ++j) row[j] = e[j] * inv;
        }
        __syncthreads();

        // rsum per c
        {
            float s = 0.f;
            for (int n = k; n < KKB; n += 8) s += sm[SM_R + n * 33 + c];
            #pragma unroll
            for (int d = 4; d; d >>= 1) s += __shfl_down_sync(0xffffffffu, s, d, 8);
            if (k == 0) {
                sm[SM_RSUM + c] = s;
                sm[SM_INVR + c] = 1.0f / (s + EPS);
            }
        }
        __syncthreads();
    }

    // ---- outputs: p_out (288*512 floats) then a_out (288*32 floats) ----
    for (int idx = tid; idx < 512; idx += NTHR)
        gout[(size_t)blk * 512 + idx] = sm[SM_MU + idx];
    if (tid < 32)
        gout[147456 + blk * 32 + tid] = sm[SM_AOUT + tid];
}

extern "C" void kernel_launch(void* const* d_in, const int* in_sizes, int n_in,
                              void* d_out, int out_size) {
    const float* x  = (const float*)d_in[0];
    const float* a  = (const float*)d_in[1];
    const float* w  = (const float*)d_in[2];
    const float* bu = (const float*)d_in[3];
    const float* ba = (const float*)d_in[4];
    float* out = (float*)d_out;
    (void)in_sizes; (void)n_in; (void)out_size;

    const int smem_bytes = SM_TOTAL * (int)sizeof(float);  // ~67 KB
    cudaFuncSetAttribute(convcaps_kernel,
                         cudaFuncAttributeMaxDynamicSharedMemorySize, smem_bytes);
    convcaps_kernel<<<288, NTHR, smem_bytes>>>(x, a, w, bu, ba, out);
}

// round 3
// speedup vs baseline: 2.6729x; 2.6729x over previous
#include <cuda_runtime.h>

#define NTHR   256
#define KKB    288
#define EPS    1e-6f
#define LAM    1e-3f
#define LN2PI  1.8378770664093453f

// shared-memory float offsets
#define SM_POSE 0                     // 288*20 = 5760
#define SM_ACT  (KKB*20)              // 5760, size 288
#define SM_RED  (SM_ACT + KKB)        // 6048, size 33*256 = 8448
#define SM_MU   (SM_RED + 33*256)     // 14496, size 32*17 = 544
#define SM_ISIG (SM_MU + 544)         // 15040, size 544
#define SM_AOUT (SM_ISIG + 544)       // 15584, size 32
#define SM_CC   (SM_AOUT + 32)        // 15616, size 32
#define SM_TOTAL (SM_CC + 32)         // 15648 floats = 62592 bytes

// transposed weights: float4 index = n*128 + q*32 + c  (q = matrix row of W_nc)
__device__ float4 g_wt[36864];

__global__ void transpose_w_kernel(const float* __restrict__ w) {
    int j = blockIdx.x * 256 + threadIdx.x;          // coalesced writes
    if (j < 147456) {
        int n = j >> 9, r = j & 511;
        int q = r >> 7, c = (r >> 2) & 31, e = r & 3;
        ((float*)g_wt)[j] = w[n * 512 + c * 16 + q * 4 + e];
    }
}

__device__ __forceinline__ float wmax32(float v) {
    #pragma unroll
    for (int d = 16; d; d >>= 1) v = fmaxf(v, __shfl_xor_sync(0xffffffffu, v, d));
    return v;
}
__device__ __forceinline__ float wsum32(float v) {
    #pragma unroll
    for (int d = 16; d; d >>= 1) v += __shfl_xor_sync(0xffffffffu, v, d);
    return v;
}

__device__ __forceinline__ void compute_v(const float* __restrict__ sm, int n, int c,
                                          float* __restrict__ v) {
    const int base = n * 128 + c;
    float4 w0 = __ldg(&g_wt[base]);
    float4 w1 = __ldg(&g_wt[base + 32]);
    float4 w2 = __ldg(&g_wt[base + 64]);
    float4 w3 = __ldg(&g_wt[base + 96]);
    const float4* pr = (const float4*)(sm + SM_POSE + n * 20);
    #pragma unroll
    for (int i = 0; i < 4; ++i) {
        float4 p = pr[i];
        v[i*4+0] = fmaf(p.x, w0.x, fmaf(p.y, w1.x, fmaf(p.z, w2.x, p.w * w3.x)));
        v[i*4+1] = fmaf(p.x, w0.y, fmaf(p.y, w1.y, fmaf(p.z, w2.y, p.w * w3.y)));
        v[i*4+2] = fmaf(p.x, w0.z, fmaf(p.y, w1.z, fmaf(p.z, w2.z, p.w * w3.z)));
        v[i*4+3] = fmaf(p.x, w0.w, fmaf(p.y, w1.w, fmaf(p.z, w2.w, p.w * w3.w)));
    }
}

__device__ __forceinline__ void store_red(float* __restrict__ sm, int warp, int c,
                                          const float* __restrict__ S1,
                                          const float* __restrict__ S2, float rs) {
    float* base = sm + SM_RED + warp * 32 + c;
    #pragma unroll
    for (int p = 0; p < 16; ++p) {
        base[p * 256]        = S1[p];
        base[(p + 16) * 256] = S2[p];
    }
    base[32 * 256] = rs;
}

__device__ __forceinline__ void finalize(float* __restrict__ sm, int tid,
                                         const float* __restrict__ gbu,
                                         const float* __restrict__ gba) {
    if (tid < 32) {
        const int c = tid;
        float rsum = 0.f;
        #pragma unroll
        for (int w = 0; w < 8; ++w) rsum += sm[SM_RED + 32 * 256 + w * 32 + c];
        float inv = __fdividef(1.0f, rsum + EPS);
        float sumlog = 0.f;
        #pragma unroll
        for (int p = 0; p < 16; ++p) {
            float s1 = 0.f, s2 = 0.f;
            #pragma unroll
            for (int w = 0; w < 8; ++w) {
                s1 += sm[SM_RED + p * 256        + w * 32 + c];
                s2 += sm[SM_RED + (p + 16) * 256 + w * 32 + c];
            }
            float mu = s1 * inv;
            float sg = (s2 - 2.f * mu * s1 + mu * mu * rsum) * inv + EPS;
            sm[SM_MU   + c * 17 + p] = mu;
            sm[SM_ISIG + c * 17 + p] = __fdividef(0.5f, sg);
            sumlog += __logf(sg);
        }
        float cost = rsum * (16.f * gbu[c] + 0.5f * sumlog);
        float ao = __fdividef(1.f, 1.f + __expf(LAM * (cost - gba[c])));
        sm[SM_AOUT + c] = ao;
        sm[SM_CC + c]   = __logf(ao) - 0.5f * sumlog - 8.f * LN2PI;
    }
}

__global__ void __launch_bounds__(NTHR, 2)
convcaps_kernel(const float* __restrict__ gx, const float* __restrict__ ga,
                const float* __restrict__ gbu, const float* __restrict__ gba,
                float* __restrict__ gout)
{
    extern __shared__ float sm[];
    const int tid  = threadIdx.x;
    const int warp = tid >> 5;
    const int c    = tid & 31;
    const int blk  = blockIdx.x;           // b*36 + h*6 + w
    const int b    = blk / 36;
    const int hw   = blk - b * 36;
    const int h2   = (hw / 6) * 2;
    const int w2   = (hw % 6) * 2;

    // ---- load pose patch (288 rows x 16 floats, padded to 20) + activations ----
    for (int idx = tid; idx < KKB * 4; idx += NTHR) {
        int n = idx >> 2, q = idx & 3;
        int ki = n / 96; int rem = n - ki * 96;
        int kj = rem >> 5; int bi = rem & 31;
        const float4* src = (const float4*)(gx +
            (size_t)((b * 14 + h2 + ki) * 14 + (w2 + kj)) * 512 + bi * 16);
        *(float4*)(sm + SM_POSE + n * 20 + q * 4) = src[q];
    }
    for (int n = tid; n < KKB; n += NTHR) {
        int ki = n / 96; int rem = n - ki * 96;
        int kj = rem >> 5; int bi = rem & 31;
        sm[SM_ACT + n] = ga[((b * 14 + h2 + ki) * 14 + (w2 + kj)) * 32 + bi];
    }
    __syncthreads();

    float S1[16], S2[16], rs;

    // ================= pass 0: M-step with uniform r = act/32 =================
    #pragma unroll
    for (int p = 0; p < 16; ++p) { S1[p] = 0.f; S2[p] = 0.f; }
    rs = 0.f;
    for (int i = 0; i < 36; ++i) {
        int n = warp + 8 * i;
        float v[16];
        compute_v(sm, n, c, v);
        float r = sm[SM_ACT + n] * (1.0f / 32.0f);
        rs += r;
        #pragma unroll
        for (int p = 0; p < 16; ++p) {
            float rv = r * v[p];
            S1[p] += rv;
            S2[p] = fmaf(rv, v[p], S2[p]);
        }
    }
    store_red(sm, warp, c, S1, S2, rs);
    __syncthreads();
    finalize(sm, tid, gbu, gba);
    __syncthreads();

    // ================= 2 fused E+M passes =================
    for (int it = 0; it < 2; ++it) {
        float mur[16], isr[16];
        #pragma unroll
        for (int p = 0; p < 16; ++p) {
            mur[p] = sm[SM_MU   + c * 17 + p];
            isr[p] = sm[SM_ISIG + c * 17 + p];
        }
        const float ccst = sm[SM_CC + c];
        #pragma unroll
        for (int p = 0; p < 16; ++p) { S1[p] = 0.f; S2[p] = 0.f; }
        rs = 0.f;

        for (int i = 0; i < 36; ++i) {
            int n = warp + 8 * i;
            float v[16];
            compute_v(sm, n, c, v);
            // E: log-likelihood distance
            float dist = 0.f;
            #pragma unroll
            for (int p = 0; p < 16; ++p) {
                float d = v[p] - mur[p];
                dist = fmaf(d, d * isr[p], dist);
            }
            float lnap = ccst - dist;
            // softmax over c (the 32 lanes of this warp)
            float m = wmax32(lnap);
            float e = __expf(lnap - m);
            float s = wsum32(e);
            float r = __fdividef(e, s);
            // M accumulate (unnormalized)
            rs += r;
            #pragma unroll
            for (int p = 0; p < 16; ++p) {
                float rv = r * v[p];
                S1[p] += rv;
                S2[p] = fmaf(rv, v[p], S2[p]);
            }
        }
        store_red(sm, warp, c, S1, S2, rs);
        __syncthreads();
        finalize(sm, tid, gbu, gba);
        __syncthreads();
    }

    // ---- outputs: p_out (288*512 floats) then a_out (288*32 floats) ----
    for (int idx = tid; idx < 512; idx += NTHR) {
        int co = idx >> 4, p = idx & 15;
        gout[(size_t)blk * 512 + idx] = sm[SM_MU + co * 17 + p];
    }
    if (tid < 32)
        gout[147456 + blk * 32 + tid] = sm[SM_AOUT + tid];
}

extern "C" void kernel_launch(void* const* d_in, const int* in_sizes, int n_in,
                              void* d_out, int out_size) {
    const float* x  = (const float*)d_in[0];
    const float* a  = (const float*)d_in[1];
    const float* w  = (const float*)d_in[2];
    const float* bu = (const float*)d_in[3];
    const float* ba = (const float*)d_in[4];
    float* out = (float*)d_out;
    (void)in_sizes; (void)n_in; (void)out_size;

    transpose_w_kernel<<<576, 256>>>(w);

    const int smem_bytes = SM_TOTAL * (int)sizeof(float);  // 62592 B
    cudaFuncSetAttribute(convcaps_kernel,
                         cudaFuncAttributeMaxDynamicSharedMemorySize, smem_bytes);
    convcaps_kernel<<<288, NTHR, smem_bytes>>>(x, a, bu, ba, out);
}

// round 4
// speedup vs baseline: 3.0623x; 1.1457x over previous
#include <cuda_runtime.h>

#define NTHR   256
#define KKB    288
#define EPS    1e-6f
#define LAM    1e-3f
#define LN2PI  1.8378770664093453f

// shared-memory float offsets
#define SM_POSE 0                       // 288*32 dup-packed = 9216
#define SM_ACT  (KKB*32)                // 9216, size 288
#define SM_RED  (SM_ACT + KKB)          // 9504, 33 rows * 257 = 8481
#define SM_NMU  (SM_RED + 33*257 + 1)   // 17986 (even, u64-aligned), 32*18 = 576
#define SM_IS   (SM_NMU + 576)          // 18562, 576
#define SM_AOUT (SM_IS + 576)           // 19138, 32
#define SM_CC   (SM_AOUT + 32)          // 19170, 32
#define SM_TOTAL (SM_CC + 32)           // 19202 floats = 76808 bytes

// transposed weights: float4 index = n*128 + q*32 + c  (q = row of W_nc, cols 0..3)
__device__ float4 g_wt[36864];

__global__ void transpose_w_kernel(const float* __restrict__ w) {
    int j = blockIdx.x * 256 + threadIdx.x;          // coalesced writes
    if (j < 147456) {
        int n = j >> 9, r = j & 511;
        int q = r >> 7, c = (r >> 2) & 31, e = r & 3;
        ((float*)g_wt)[j] = w[n * 512 + c * 16 + q * 4 + e];
    }
}

// ---------- packed f32x2 primitives ----------
typedef unsigned long long u64;

__device__ __forceinline__ u64 fma2(u64 a, u64 b, u64 c) {
    u64 d; asm("fma.rn.f32x2 %0, %1, %2, %3;" : "=l"(d) : "l"(a), "l"(b), "l"(c));
    return d;
}
__device__ __forceinline__ u64 mul2(u64 a, u64 b) {
    u64 d; asm("mul.rn.f32x2 %0, %1, %2;" : "=l"(d) : "l"(a), "l"(b));
    return d;
}
__device__ __forceinline__ u64 add2(u64 a, u64 b) {
    u64 d; asm("add.rn.f32x2 %0, %1, %2;" : "=l"(d) : "l"(a), "l"(b));
    return d;
}
__device__ __forceinline__ u64 pack2(float lo, float hi) {
    u64 r; asm("mov.b64 %0, {%1, %2};" : "=l"(r) : "f"(lo), "f"(hi)); return r;
}
__device__ __forceinline__ float2 unpack2(u64 v) {
    float2 r; asm("mov.b64 {%0, %1}, %2;" : "=f"(r.x), "=f"(r.y) : "l"(v)); return r;
}

__device__ __forceinline__ float wmax32(float v) {
    #pragma unroll
    for (int d = 16; d; d >>= 1) v = fmaxf(v, __shfl_xor_sync(0xffffffffu, v, d));
    return v;
}
__device__ __forceinline__ float wsum32(float v) {
    #pragma unroll
    for (int d = 16; d; d >>= 1) v += __shfl_xor_sync(0xffffffffu, v, d);
    return v;
}

// v pairs: v2[2i]   = (v[i*4+0], v[i*4+1]),  v2[2i+1] = (v[i*4+2], v[i*4+3])
__device__ __forceinline__ void compute_v2(const float* __restrict__ sm, int n, int c,
                                           u64* __restrict__ v2) {
    const ulonglong2* __restrict__ W = (const ulonglong2*)g_wt + ((size_t)n * 128 + c);
    ulonglong2 w0 = W[0], w1 = W[32], w2 = W[64], w3 = W[96];
    const ulonglong2* __restrict__ P = (const ulonglong2*)(sm + SM_POSE + n * 32);
    #pragma unroll
    for (int i = 0; i < 4; ++i) {
        ulonglong2 pa = P[2 * i];         // (p4i,p4i) , (p4i+1,p4i+1)
        ulonglong2 pb = P[2 * i + 1];     // (p4i+2,..), (p4i+3,..)
        v2[2*i]   = fma2(pa.x, w0.x, fma2(pa.y, w1.x, fma2(pb.x, w2.x, mul2(pb.y, w3.x))));
        v2[2*i+1] = fma2(pa.x, w0.y, fma2(pa.y, w1.y, fma2(pb.x, w2.y, mul2(pb.y, w3.y))));
    }
}

__device__ __forceinline__ void macc2(float r, const u64* __restrict__ v2,
                                      u64* __restrict__ S1, u64* __restrict__ S2) {
    u64 r2 = pack2(r, r);
    #pragma unroll
    for (int pp = 0; pp < 8; ++pp) {
        u64 rv = mul2(r2, v2[pp]);
        S1[pp] = add2(S1[pp], rv);
        S2[pp] = fma2(rv, v2[pp], S2[pp]);
    }
}

__device__ __forceinline__ void store_red(float* __restrict__ sm, int warp, int c,
                                          const u64* __restrict__ S1,
                                          const u64* __restrict__ S2, float rs) {
    float* base = sm + SM_RED + warp * 32 + c;
    #pragma unroll
    for (int pp = 0; pp < 8; ++pp) {
        float2 a = unpack2(S1[pp]);
        float2 b = unpack2(S2[pp]);
        base[(2*pp)   * 257] = a.x;
        base[(2*pp+1) * 257] = a.y;
        base[(2*pp+16) * 257] = b.x;
        base[(2*pp+17) * 257] = b.y;
    }
    base[32 * 257] = rs;
}

// parallel finalize: 32 groups of 8 lanes; group g = capsule c, lane handles 2 p's
__device__ __forceinline__ void finalize(float* __restrict__ sm, int tid,
                                         const float* __restrict__ gbu,
                                         const float* __restrict__ gba) {
    const int g = tid >> 3, l8 = tid & 7;
    float rsum = 0.f;
    #pragma unroll
    for (int w = 0; w < 8; ++w) rsum += sm[SM_RED + 32 * 257 + w * 32 + g];
    float inv = __fdividef(1.0f, rsum + EPS);
    float plog = 0.f;
    #pragma unroll
    for (int t = 0; t < 2; ++t) {
        int p = 2 * l8 + t;
        float s1 = 0.f, s2 = 0.f;
        #pragma unroll
        for (int w = 0; w < 8; ++w) {
            s1 += sm[SM_RED + p * 257        + w * 32 + g];
            s2 += sm[SM_RED + (p + 16) * 257 + w * 32 + g];
        }
        float mu = s1 * inv;
        float sg = (s2 - 2.f * mu * s1 + mu * mu * rsum) * inv + EPS;
        sm[SM_NMU + g * 18 + p] = -mu;
        sm[SM_IS  + g * 18 + p] = __fdividef(0.5f, sg);
        plog += __logf(sg);
    }
    #pragma unroll
    for (int d = 1; d < 8; d <<= 1) plog += __shfl_xor_sync(0xffffffffu, plog, d);
    if (l8 == 0) {
        float cost = rsum * (16.f * gbu[g] + 0.5f * plog);
        float ao = __fdividef(1.f, 1.f + __expf(LAM * (cost - gba[g])));
        sm[SM_AOUT + g] = ao;
        sm[SM_CC + g]   = __logf(ao) - 0.5f * plog - 8.f * LN2PI;
    }
}

__global__ void __launch_bounds__(NTHR, 2)
convcaps_kernel(const float* __restrict__ gx, const float* __restrict__ ga,
                const float* __restrict__ gbu, const float* __restrict__ gba,
                float* __restrict__ gout)
{
    extern __shared__ float sm[];
    const int tid  = threadIdx.x;
    const int warp = tid >> 5;
    const int c    = tid & 31;
    const int blk  = blockIdx.x;           // b*36 + h*6 + w
    const int b    = blk / 36;
    const int hw   = blk - b * 36;
    const int h2   = (hw / 6) * 2;
    const int w2   = (hw % 6) * 2;

    // ---- load pose patch duplicated: row n = [p0,p0,p1,p1,...,p15,p15] ----
    for (int idx = tid; idx < KKB * 16; idx += NTHR) {
        int n = idx >> 4, q = idx & 15;
        int ki = n / 96; int rem = n - ki * 96;
        int kj = rem >> 5; int bi = rem & 31;
        float f = gx[(size_t)((b * 14 + h2 + ki) * 14 + (w2 + kj)) * 512 + bi * 16 + q];
        *(float2*)(sm + SM_POSE + n * 32 + 2 * q) = make_float2(f, f);
    }
    for (int n = tid; n < KKB; n += NTHR) {
        int ki = n / 96; int rem = n - ki * 96;
        int kj = rem >> 5; int bi = rem & 31;
        sm[SM_ACT + n] = ga[((b * 14 + h2 + ki) * 14 + (w2 + kj)) * 32 + bi];
    }
    __syncthreads();

    u64 S1[8], S2[8];
    float rs;

    // ================= pass 0: M-step with uniform r = act/32 =================
    #pragma unroll
    for (int pp = 0; pp < 8; ++pp) { S1[pp] = 0ull; S2[pp] = 0ull; }
    rs = 0.f;
    for (int i = 0; i < 36; ++i) {
        int n = warp + 8 * i;
        u64 v2[8];
        compute_v2(sm, n, c, v2);
        float r = sm[SM_ACT + n] * (1.0f / 32.0f);
        rs += r;
        macc2(r, v2, S1, S2);
    }
    store_red(sm, warp, c, S1, S2, rs);
    __syncthreads();
    finalize(sm, tid, gbu, gba);
    __syncthreads();

    // ================= 2 fused E+M passes =================
    for (int it = 0; it < 2; ++it) {
        u64 nmu2[8], is2[8];
        #pragma unroll
        for (int pp = 0; pp < 8; ++pp) {
            nmu2[pp] = *(const u64*)(sm + SM_NMU + c * 18 + 2 * pp);
            is2[pp]  = *(const u64*)(sm + SM_IS  + c * 18 + 2 * pp);
        }
        const float ccst = sm[SM_CC + c];
        #pragma unroll
        for (int pp = 0; pp < 8; ++pp) { S1[pp] = 0ull; S2[pp] = 0ull; }
        rs = 0.f;

        for (int i = 0; i < 36; ++i) {
            int n = warp + 8 * i;
            u64 v2[8];
            compute_v2(sm, n, c, v2);
            // E: Mahalanobis distance (packed)
            u64 dist2 = 0ull;
            #pragma unroll
            for (int pp = 0; pp < 8; ++pp) {
                u64 d = add2(v2[pp], nmu2[pp]);
                dist2 = fma2(d, mul2(d, is2[pp]), dist2);
            }
            float2 df = unpack2(dist2);
            float lnap = ccst - (df.x + df.y);
            // softmax over c (32 lanes)
            float m = wmax32(lnap);
            float e = __expf(lnap - m);
            float s = wsum32(e);
            float r = __fdividef(e, s);
            rs += r;
            macc2(r, v2, S1, S2);
        }
        store_red(sm, warp, c, S1, S2, rs);
        __syncthreads();
        finalize(sm, tid, gbu, gba);
        __syncthreads();
    }

    // ---- outputs: p_out (288*512 floats) then a_out (288*32 floats) ----
    for (int idx = tid; idx < 512; idx += NTHR) {
        int co = idx >> 4, p = idx & 15;
        gout[(size_t)blk * 512 + idx] = -sm[SM_NMU + co * 18 + p];
    }
    if (tid < 32)
        gout[147456 + blk * 32 + tid] = sm[SM_AOUT + tid];
}

extern "C" void kernel_launch(void* const* d_in, const int* in_sizes, int n_in,
                              void* d_out, int out_size) {
    const float* x  = (const float*)d_in[0];
    const float* a  = (const float*)d_in[1];
    const float* w  = (const float*)d_in[2];
    const float* bu = (const float*)d_in[3];
    const float* ba = (const float*)d_in[4];
    float* out = (float*)d_out;
    (void)in_sizes; (void)n_in; (void)out_size;

    transpose_w_kernel<<<576, 256>>>(w);

    const int smem_bytes = SM_TOTAL * (int)sizeof(float);  // 76808 B
    cudaFuncSetAttribute(convcaps_kernel,
                         cudaFuncAttributeMaxDynamicSharedMemorySize, smem_bytes);
    convcaps_kernel<<<288, NTHR, smem_bytes>>>(x, a, bu, ba, out);
}

// round 6
// speedup vs baseline: 3.3237x; 1.0854x over previous
#include <cuda_runtime.h>

#define NTHR   256
#define KKB    288
#define EPS    1e-6f
#define LAM    1e-3f
#define LN2PI  1.8378770664093453f

// shared-memory float offsets
#define SM_POSE 0                       // 288*32 dup-packed = 9216
#define SM_ACT  (KKB*32)                // 9216, size 288
#define SM_RED  (SM_ACT + KKB)          // 9504, 33 rows * 257 = 8481
#define SM_NMU  (SM_RED + 33*257 + 1)   // 17986 (even, u64-aligned), 32*18 = 576
#define SM_IS   (SM_NMU + 576)          // 18562, 576
#define SM_AOUT (SM_IS + 576)           // 19138, 32
#define SM_CC   (SM_AOUT + 32)          // 19170, 32
#define SM_TOTAL (SM_CC + 32)           // 19202 floats = 76808 bytes

// transposed weights: float4 index = n*128 + q*32 + c  (q = row of W_nc, cols 0..3)
__device__ float4 g_wt[36864];

__global__ void transpose_w_kernel(const float* __restrict__ w) {
    int j = blockIdx.x * 256 + threadIdx.x;          // coalesced writes
    if (j < 147456) {
        int n = j >> 9, r = j & 511;
        int q = r >> 7, c = (r >> 2) & 31, e = r & 3;
        ((float*)g_wt)[j] = w[n * 512 + c * 16 + q * 4 + e];
    }
}

// ---------- packed f32x2 primitives ----------
typedef unsigned long long u64;

__device__ __forceinline__ u64 fma2(u64 a, u64 b, u64 c) {
    u64 d; asm("fma.rn.f32x2 %0, %1, %2, %3;" : "=l"(d) : "l"(a), "l"(b), "l"(c));
    return d;
}
__device__ __forceinline__ u64 mul2(u64 a, u64 b) {
    u64 d; asm("mul.rn.f32x2 %0, %1, %2;" : "=l"(d) : "l"(a), "l"(b));
    return d;
}
__device__ __forceinline__ u64 add2(u64 a, u64 b) {
    u64 d; asm("add.rn.f32x2 %0, %1, %2;" : "=l"(d) : "l"(a), "l"(b));
    return d;
}
__device__ __forceinline__ u64 pack2(float lo, float hi) {
    u64 r; asm("mov.b64 %0, {%1, %2};" : "=l"(r) : "f"(lo), "f"(hi)); return r;
}
__device__ __forceinline__ float2 unpack2(u64 v) {
    float2 r; asm("mov.b64 {%0, %1}, %2;" : "=f"(r.x), "=f"(r.y) : "l"(v)); return r;
}

// warp max of a float via integer redux (sm_80+): order-preserving u32 mapping
__device__ __forceinline__ float redmax32f(float v) {
    int i = __float_as_int(v);
    unsigned u = (unsigned)(i ^ ((i >> 31) | 0x80000000));
    unsigned m;
    asm("redux.sync.max.u32 %0, %1, 0xffffffff;" : "=r"(m) : "r"(u));
    int mi = (int)(m ^ ((~(int)m >> 31) | 0x80000000));
    return __int_as_float(mi);
}
// interleaved butterfly sums for two independent values
__device__ __forceinline__ void wsum32x2(float& a, float& b) {
    #pragma unroll
    for (int d = 16; d; d >>= 1) {
        a += __shfl_xor_sync(0xffffffffu, a, d);
        b += __shfl_xor_sync(0xffffffffu, b, d);
    }
}

// v pairs: v2[2i] = (v[4i+0], v[4i+1]), v2[2i+1] = (v[4i+2], v[4i+3])
__device__ __forceinline__ void compute_v2(const float* __restrict__ sm, int n, int c,
                                           u64* __restrict__ v2) {
    const ulonglong2* __restrict__ W = (const ulonglong2*)g_wt + ((size_t)n * 128 + c);
    ulonglong2 w0 = W[0], w1 = W[32], w2 = W[64], w3 = W[96];
    const ulonglong2* __restrict__ P = (const ulonglong2*)(sm + SM_POSE + n * 32);
    #pragma unroll
    for (int i = 0; i < 4; ++i) {
        ulonglong2 pa = P[2 * i];
        ulonglong2 pb = P[2 * i + 1];
        v2[2*i]   = fma2(pa.x, w0.x, fma2(pa.y, w1.x, fma2(pb.x, w2.x, mul2(pb.y, w3.x))));
        v2[2*i+1] = fma2(pa.x, w0.y, fma2(pa.y, w1.y, fma2(pb.x, w2.y, mul2(pb.y, w3.y))));
    }
}

__device__ __forceinline__ float dist16(const u64* __restrict__ v2,
                                        const u64* __restrict__ nmu2,
                                        const u64* __restrict__ is2) {
    u64 acc = 0ull;
    #pragma unroll
    for (int pp = 0; pp < 8; ++pp) {
        u64 d = add2(v2[pp], nmu2[pp]);
        acc = fma2(d, mul2(d, is2[pp]), acc);
    }
    float2 df = unpack2(acc);
    return df.x + df.y;
}

__device__ __forceinline__ void macc2(float r, const u64* __restrict__ v2,
                                      u64* __restrict__ S1, u64* __restrict__ S2) {
    u64 r2 = pack2(r, r);
    #pragma unroll
    for (int pp = 0; pp < 8; ++pp) {
        u64 rv = mul2(r2, v2[pp]);
        S1[pp] = add2(S1[pp], rv);
        S2[pp] = fma2(rv, v2[pp], S2[pp]);
    }
}

__device__ __forceinline__ void store_red(float* __restrict__ sm, int warp, int c,
                                          const u64* __restrict__ S1,
                                          const u64* __restrict__ S2, float rs) {
    float* base = sm + SM_RED + warp * 32 + c;
    #pragma unroll
    for (int pp = 0; pp < 8; ++pp) {
        float2 a = unpack2(S1[pp]);
        float2 b = unpack2(S2[pp]);
        base[(2*pp)    * 257] = a.x;
        base[(2*pp+1)  * 257] = a.y;
        base[(2*pp+16) * 257] = b.x;
        base[(2*pp+17) * 257] = b.y;
    }
    base[32 * 257] = rs;
}

// parallel finalize: 32 groups of 8 lanes; group g = capsule c, lane handles 2 p's
__device__ __forceinline__ void finalize(float* __restrict__ sm, int tid,
                                         const float* __restrict__ gbu,
                                         const float* __restrict__ gba) {
    const int g = tid >> 3, l8 = tid & 7;
    float rsum = 0.f;
    #pragma unroll
    for (int w = 0; w < 8; ++w) rsum += sm[SM_RED + 32 * 257 + w * 32 + g];
    float inv = __fdividef(1.0f, rsum + EPS);
    float plog = 0.f;
    #pragma unroll
    for (int t = 0; t < 2; ++t) {
        int p = 2 * l8 + t;
        float s1 = 0.f, s2 = 0.f;
        #pragma unroll
        for (int w = 0; w < 8; ++w) {
            s1 += sm[SM_RED + p * 257        + w * 32 + g];
            s2 += sm[SM_RED + (p + 16) * 257 + w * 32 + g];
        }
        float mu = s1 * inv;
        float sg = (s2 - 2.f * mu * s1 + mu * mu * rsum) * inv + EPS;
        sm[SM_NMU + g * 18 + p] = -mu;
        sm[SM_IS  + g * 18 + p] = __fdividef(0.5f, sg);
        plog += __logf(sg);
    }
    #pragma unroll
    for (int d = 1; d < 8; d <<= 1) plog += __shfl_xor_sync(0xffffffffu, plog, d);
    if (l8 == 0) {
        float cost = rsum * (16.f * gbu[g] + 0.5f * plog);
        float ao = __fdividef(1.f, 1.f + __expf(LAM * (cost - gba[g])));
        sm[SM_AOUT + g] = ao;
        sm[SM_CC + g]   = __logf(ao) - 0.5f * plog - 8.f * LN2PI;
    }
}

__global__ void __launch_bounds__(NTHR, 2)
convcaps_kernel(const float* __restrict__ gx, const float* __restrict__ ga,
                const float* __restrict__ gbu, const float* __restrict__ gba,
                float* __restrict__ gout)
{
    extern __shared__ float sm[];
    const int tid  = threadIdx.x;
    const int warp = tid >> 5;
    const int c    = tid & 31;
    const int blk  = blockIdx.x;           // b*36 + h*6 + w
    const int b    = blk / 36;
    const int hw   = blk - b * 36;
    const int h2   = (hw / 6) * 2;
    const int w2   = (hw % 6) * 2;

    // ---- load pose patch duplicated: row n = [p0,p0,p1,p1,...,p15,p15] ----
    for (int idx = tid; idx < KKB * 16; idx += NTHR) {
        int n = idx >> 4, q = idx & 15;
        int ki = n / 96; int rem = n - ki * 96;
        int kj = rem >> 5; int bi = rem & 31;
        float f = gx[(size_t)((b * 14 + h2 + ki) * 14 + (w2 + kj)) * 512 + bi * 16 + q];
        *(float2*)(sm + SM_POSE + n * 32 + 2 * q) = make_float2(f, f);
    }
    for (int n = tid; n < KKB; n += NTHR) {
        int ki = n / 96; int rem = n - ki * 96;
        int kj = rem >> 5; int bi = rem & 31;
        sm[SM_ACT + n] = ga[((b * 14 + h2 + ki) * 14 + (w2 + kj)) * 32 + bi];
    }
    __syncthreads();

    u64 S1[8], S2[8];
    float rs;

    // ================= pass 0: M-step with uniform r = act/32 =================
    #pragma unroll
    for (int pp = 0; pp < 8; ++pp) { S1[pp] = 0ull; S2[pp] = 0ull; }
    rs = 0.f;
    for (int i = 0; i < 36; i += 2) {
        int n0 = warp + 8 * i, n1 = n0 + 8;
        u64 va[8], vb[8];
        compute_v2(sm, n0, c, va);
        compute_v2(sm, n1, c, vb);
        float r0 = sm[SM_ACT + n0] * (1.0f / 32.0f);
        float r1 = sm[SM_ACT + n1] * (1.0f / 32.0f);
        rs += r0 + r1;
        macc2(r0, va, S1, S2);
        macc2(r1, vb, S1, S2);
    }
    store_red(sm, warp, c, S1, S2, rs);
    __syncthreads();
    finalize(sm, tid, gbu, gba);
    __syncthreads();

    // ================= 2 fused E+M passes (2-way interleaved) =================
    for (int it = 0; it < 2; ++it) {
        u64 nmu2[8], is2[8];
        #pragma unroll
        for (int pp = 0; pp < 8; ++pp) {
            nmu2[pp] = *(const u64*)(sm + SM_NMU + c * 18 + 2 * pp);
            is2[pp]  = *(const u64*)(sm + SM_IS  + c * 18 + 2 * pp);
        }
        const float ccst = sm[SM_CC + c];
        #pragma unroll
        for (int pp = 0; pp < 8; ++pp) { S1[pp] = 0ull; S2[pp] = 0ull; }
        rs = 0.f;

        for (int i = 0; i < 36; i += 2) {
            int n0 = warp + 8 * i, n1 = n0 + 8;
            u64 va[8], vb[8];
            compute_v2(sm, n0, c, va);
            compute_v2(sm, n1, c, vb);
            float l0 = ccst - dist16(va, nmu2, is2);
            float l1 = ccst - dist16(vb, nmu2, is2);
            float m0 = redmax32f(l0);
            float m1 = redmax32f(l1);
            float e0 = __expf(l0 - m0);
            float e1 = __expf(l1 - m1);
            float s0 = e0, s1 = e1;
            wsum32x2(s0, s1);
            float r0 = __fdividef(e0, s0);
            float r1 = __fdividef(e1, s1);
            rs += r0 + r1;
            macc2(r0, va, S1, S2);
            macc2(r1, vb, S1, S2);
        }
        store_red(sm, warp, c, S1, S2, rs);
        __syncthreads();
        finalize(sm, tid, gbu, gba);
        __syncthreads();
    }

    // ---- outputs: p_out (288*512 floats) then a_out (288*32 floats) ----
    for (int idx = tid; idx < 512; idx += NTHR) {
        int co = idx >> 4, p = idx & 15;
        gout[(size_t)blk * 512 + idx] = -sm[SM_NMU + co * 18 + p];
    }
    if (tid < 32)
        gout[147456 + blk * 32 + tid] = sm[SM_AOUT + tid];
}

extern "C" void kernel_launch(void* const* d_in, const int* in_sizes, int n_in,
                              void* d_out, int out_size) {
    const float* x  = (const float*)d_in[0];
    const float* a  = (const float*)d_in[1];
    const float* w  = (const float*)d_in[2];
    const float* bu = (const float*)d_in[3];
    const float* ba = (const float*)d_in[4];
    float* out = (float*)d_out;
    (void)in_sizes; (void)n_in; (void)out_size;

    transpose_w_kernel<<<576, 256>>>(w);

    const int smem_bytes = SM_TOTAL * (int)sizeof(float);  // 76808 B
    cudaFuncSetAttribute(convcaps_kernel,
                         cudaFuncAttributeMaxDynamicSharedMemorySize, smem_bytes);
    convcaps_kernel<<<288, NTHR, smem_bytes>>>(x, a, bu, ba, out);
}